// round 10
// baseline (speedup 1.0000x reference)
#include <cuda_runtime.h>
#include <cuda_fp16.h>
#include <mma.h>
#include <cstdint>
#include <cstddef>

// ---------------- arch-conditional path selection ----------------
// tcgen05 is only legal when compiling for sm_103a / sm_100a (or family-specific
// targets). In any plain compute_10x pass the tcgen05 kernel body compiles to
// empty and the wmma fallback body is compiled instead. Host launches both;
// exactly one does work in the loaded image.
#if defined(__CUDA_ARCH__) && \
    (defined(__CUDA_ARCH_FEAT_SM103_ALL) || defined(__CUDA_ARCH_FEAT_SM100_ALL) || \
     defined(__CUDA_ARCH_SPECIFIC__) || defined(__CUDA_ARCH_FAMILY_SPECIFIC__))
#define TC_PATH 1
#else
#define TC_PATH 0
#endif

// ---------------- problem dims ----------------
#define ROWS_T 16384   // B*S
#define DK     1024    // d_model (K)
#define OUTD   4096    // out_dim (N total)
#define NEXP   2       // modalities

// ---------------- tcgen05 tiling ----------------
#define MT 128         // M tile (token rows)
#define NT 256         // N tile (out cols) = 2 x N=128 MMA atoms
#define KC 64          // K chunk (64 halves = 128B SW128 rows)
#define NKC (DK / KC)  // 16
#define ST 2           // pipeline stages

#define STAGE_A_BYTES (MT * 128)            // 16 KB
#define STAGE_B_BYTES (NT * 128)            // 32 KB
#define STAGE_BYTES   (STAGE_A_BYTES + STAGE_B_BYTES)
#define SMEM_TOTAL    (2048 + ST * STAGE_BYTES)   // 100352 B -> 2 CTAs/SM

// idesc kind::f16: dtype=F32 (bit4), atype=btype=F16 (0), N=128 -> 16<<17, M=128 -> 8<<24
#define IDESC_F16 ((1u << 4) | (16u << 17) | (8u << 24))

// ---------------- fallback (wmma) tiling ----------------
#define FB_LD    40                          // smem half leading dim (32 + 8 pad)
#define FB_TILEH (128 * FB_LD)               // halves per tile-stage
#define FB_SMEM  (4 * FB_TILEH * 2 + 8 * 16 * 20 * 4)   // 40960 + 10240 = 51200 B

// ---------------- scratch (fp16 operands) ----------------
__device__ __half g_Xh[(size_t)ROWS_T * DK];          // X cast to fp16, row-major [ROWS, DK]
__device__ __half g_Wt[(size_t)NEXP * OUTD * DK];     // W transposed to [OUT, DK] K-major, fp16

// ---------------- generic helpers (legal on all targets) ----------------
__device__ __forceinline__ uint32_t smem_u32(const void* p) {
    uint32_t a;
    asm("{ .reg .u64 t; cvta.to.shared.u64 t, %1; cvt.u32.u64 %0, t; }" : "=r"(a) : "l"(p));
    return a;
}

#define SWZ(o) ((o) ^ (((o) >> 3) & 0x70))

__device__ __forceinline__ void cp_async16(uint32_t dst_smem, const void* src) {
    asm volatile("cp.async.cg.shared.global [%0], [%1], 16;" :: "r"(dst_smem), "l"(src));
}
#define CP_COMMIT() asm volatile("cp.async.commit_group;" ::: "memory")
#define CP_WAIT0()  asm volatile("cp.async.wait_group 0;"  ::: "memory")

__device__ __forceinline__ void mbar_init(uint32_t mbar, uint32_t count) {
    asm volatile("mbarrier.init.shared.b64 [%0], %1;" :: "r"(mbar), "r"(count) : "memory");
}

__device__ __forceinline__ void mbar_wait(uint32_t mbar, uint32_t parity) {
    asm volatile(
        "{\n\t.reg .pred P;\n"
        "WL_%=:\n\t"
        "mbarrier.try_wait.parity.acquire.cta.shared::cta.b64 P, [%0], %1, 0x989680;\n\t"
        "@P bra.uni WD_%=;\n\t"
        "bra.uni WL_%=;\n"
        "WD_%=:\n\t}"
        :: "r"(mbar), "r"(parity) : "memory");
}

// ---------------- conversion kernels (arch-independent) ----------------
__global__ void conv_x_kernel(const float* __restrict__ x) {
    size_t i = (size_t)blockIdx.x * blockDim.x + threadIdx.x;   // over n/4 float4s
    float4 v = reinterpret_cast<const float4*>(x)[i];
    __half2* o = reinterpret_cast<__half2*>(g_Xh);
    o[i * 2 + 0] = __floats2half2_rn(v.x, v.y);
    o[i * 2 + 1] = __floats2half2_rn(v.z, v.w);
}

// W [DK, OUTD] fp32 row-major  ->  g_Wt[e] [OUTD, DK] fp16 K-major (transpose + cast)
__global__ void conv_w_kernel(const float* __restrict__ W, int e) {
    __shared__ float t[32][33];
    int o0 = blockIdx.x * 32, d0 = blockIdx.y * 32;
    int tx = threadIdx.x, ty = threadIdx.y;   // (32, 8)
    #pragma unroll
    for (int j = 0; j < 32; j += 8)
        t[ty + j][tx] = W[(size_t)(d0 + ty + j) * OUTD + o0 + tx];
    __syncthreads();
    __half* Wt = g_Wt + (size_t)e * OUTD * DK;
    #pragma unroll
    for (int j = 0; j < 32; j += 8)
        Wt[(size_t)(o0 + ty + j) * DK + d0 + tx] = __float2half(t[tx][ty + j]);
}

// ===================================================================
//                    tcgen05 path (sm_103a only)
// ===================================================================
#if TC_PATH
__device__ __forceinline__ uint64_t make_desc_sw128(uint32_t addr) {
    // layout=SW128(2), version=1 (Blackwell), SBO=64 (1024B per 8-row group), LBO=1 (16B)
    const uint64_t base = (uint64_t(2) << 61) | (uint64_t(1) << 46) |
                          (uint64_t(64) << 32) | (uint64_t(1) << 16);
    return base | ((uint64_t)(addr >> 4) & 0x3FFF);
}

__device__ __forceinline__ void tcgen05_mma_f16_ss(uint32_t d_tmem, uint64_t a_desc,
                                                   uint64_t b_desc, uint32_t idesc,
                                                   uint32_t enable_d) {
    asm volatile(
        "{\n\t.reg .pred p;\n\t"
        "setp.ne.u32 p, %5, 0;\n\t"
        "tcgen05.mma.cta_group::1.kind::f16 [%0], %1, %2, %3, {%4, %4, %4, %4}, p;\n\t}"
        :: "r"(d_tmem), "l"(a_desc), "l"(b_desc), "r"(idesc), "r"(0u), "r"(enable_d)
        : "memory");
}

#define TC_COMMIT(mbar) \
    asm volatile("tcgen05.commit.cta_group::1.mbarrier::arrive::one.shared::cluster.b64 [%0];" \
                 :: "r"(mbar) : "memory")
#define TC_ALLOC(dst_smem, ncols) \
    asm volatile("tcgen05.alloc.cta_group::1.sync.aligned.shared::cta.b32 [%0], %1;" \
                 :: "r"(dst_smem), "r"(ncols) : "memory")
#define TC_DEALLOC(tmem, ncols) \
    asm volatile("tcgen05.dealloc.cta_group::1.sync.aligned.b32 %0, %1;" :: "r"(tmem), "r"(ncols))
#define TC_RELINQ() \
    asm volatile("tcgen05.relinquish_alloc_permit.cta_group::1.sync.aligned;")
#define TC_FENCE_AFTER()  asm volatile("tcgen05.fence::after_thread_sync;" ::: "memory")
#define TC_FENCE_BEFORE() asm volatile("tcgen05.fence::before_thread_sync;" ::: "memory")
#define TC_WAIT_LD()      asm volatile("tcgen05.wait::ld.sync.aligned;" ::: "memory")
#define FENCE_PROXY_ASYNC() asm volatile("fence.proxy.async.shared::cta;" ::: "memory")

#define TC_LD_32X32B_X32(r, tmem_addr) \
    asm volatile( \
        "tcgen05.ld.sync.aligned.32x32b.x32.b32 " \
        "{%0, %1, %2, %3, %4, %5, %6, %7, " \
        " %8, %9, %10, %11, %12, %13, %14, %15, " \
        " %16, %17, %18, %19, %20, %21, %22, %23, " \
        " %24, %25, %26, %27, %28, %29, %30, %31}, [%32];" \
        : "=r"((r)[0]),  "=r"((r)[1]),  "=r"((r)[2]),  "=r"((r)[3]), \
          "=r"((r)[4]),  "=r"((r)[5]),  "=r"((r)[6]),  "=r"((r)[7]), \
          "=r"((r)[8]),  "=r"((r)[9]),  "=r"((r)[10]), "=r"((r)[11]), \
          "=r"((r)[12]), "=r"((r)[13]), "=r"((r)[14]), "=r"((r)[15]), \
          "=r"((r)[16]), "=r"((r)[17]), "=r"((r)[18]), "=r"((r)[19]), \
          "=r"((r)[20]), "=r"((r)[21]), "=r"((r)[22]), "=r"((r)[23]), \
          "=r"((r)[24]), "=r"((r)[25]), "=r"((r)[26]), "=r"((r)[27]), \
          "=r"((r)[28]), "=r"((r)[29]), "=r"((r)[30]), "=r"((r)[31]) \
        : "r"(tmem_addr))

__device__ __forceinline__ void load_stage(int tid, uint32_t data_base, int stage, int kc,
                                           const __half* Asrc, const __half* Bsrc) {
    const uint32_t aBase = data_base + (uint32_t)stage * STAGE_BYTES;
    const uint32_t bBase = aBase + STAGE_A_BYTES;
    const int k0 = kc * KC;
    // A: 128 rows x 8 x 16B chunks = 1024 chunks
    #pragma unroll
    for (int t = 0; t < 8; t++) {
        int idx = tid + t * 128;          // 0..1023
        int row = idx >> 3, c = idx & 7;
        const __half* src = Asrc + (size_t)row * DK + k0 + c * 8;
        uint32_t off = (uint32_t)(row * 128 + c * 16);
        cp_async16(aBase + SWZ(off), src);
    }
    // B: 256 rows x 8 chunks = 2048 chunks
    #pragma unroll
    for (int t = 0; t < 16; t++) {
        int idx = tid + t * 128;          // 0..2047
        int row = idx >> 3, c = idx & 7;
        const __half* src = Bsrc + (size_t)row * DK + k0 + c * 8;
        uint32_t off = (uint32_t)(row * 128 + c * 16);
        cp_async16(bBase + SWZ(off), src);
    }
    CP_COMMIT();
}
#endif  // TC_PATH

__global__ __launch_bounds__(128, 2)
void motmod_gemm_kernel(const int* __restrict__ type_ids,
                        const float* __restrict__ bias0,
                        const float* __restrict__ bias1,
                        float* __restrict__ out) {
#if TC_PATH
    extern __shared__ __align__(16) char smem[];
    const uint32_t smem_base = smem_u32(smem);
    const uint32_t data_base = (smem_base + 1024u + 1023u) & ~1023u;   // 1024B-aligned tiles
    const int tid = threadIdx.x;
    const int wid = tid >> 5, lid = tid & 31;

    const int n0 = blockIdx.x * NT;
    const int m0 = blockIdx.y * MT;
    const int e  = blockIdx.z;

    const uint32_t mbar0 = smem_base + 16;          // ST mbarriers, 8B each

    if (wid == 0) {
        TC_ALLOC(smem_base, 256);                   // 256 TMEM cols for D (fp32, N=256)
        TC_RELINQ();
    }
    if (tid == 0) {
        #pragma unroll
        for (int s = 0; s < ST; s++) mbar_init(mbar0 + s * 8, 1);
    }
    __syncthreads();

    uint32_t tmem_base;
    asm volatile("ld.shared.b32 %0, [%1];" : "=r"(tmem_base) : "r"(smem_base));

    const __half* Asrc = g_Xh + (size_t)m0 * DK;
    const __half* Bsrc = g_Wt + ((size_t)e * OUTD + n0) * DK;

    load_stage(tid, data_base, 0, 0, Asrc, Bsrc);

    for (int i = 0; i < NKC; i++) {
        const int b = i & (ST - 1);
        CP_WAIT0();
        __syncthreads();

        if (tid == 0) {
            FENCE_PROXY_ASYNC();
            const uint32_t aBase = data_base + (uint32_t)b * STAGE_BYTES;
            const uint32_t bBase = aBase + STAGE_A_BYTES;
            const uint64_t ad = make_desc_sw128(aBase);
            const uint64_t bd = make_desc_sw128(bBase);
            #pragma unroll
            for (int ks = 0; ks < 4; ks++) {                  // K=16 per MMA
                const uint32_t acc = (i > 0 || ks > 0) ? 1u : 0u;
                #pragma unroll
                for (int h = 0; h < 2; h++) {                 // two N=128 halves
                    tcgen05_mma_f16_ss(tmem_base + h * 128,
                                       ad + ks * 2,
                                       bd + (uint64_t)h * 1024 + ks * 2,
                                       IDESC_F16, acc);
                }
            }
            TC_COMMIT(mbar0 + b * 8);
        }

        const int ld = i + (ST - 1);
        if (ld < NKC) {
            const int w = ld - ST;                    // chunk that last used this buffer
            if (w >= 0) mbar_wait(mbar0 + (w & (ST - 1)) * 8, (w >> 1) & 1);
            load_stage(tid, data_base, ld & (ST - 1), ld, Asrc, Bsrc);
        }
    }

    {
        const int w = NKC - 1;
        mbar_wait(mbar0 + (w & (ST - 1)) * 8, (w >> 1) & 1);
    }
    TC_FENCE_AFTER();

    // epilogue: LDTM + mask + bias + store
    const int r = m0 + wid * 32 + lid;
    const int tmask = (type_ids[r] == e);
    // FIX (R7 post-mortem): bias must be offset by this CTA's N-tile origin n0.
    // Previously indexed bias[c0+j] (n mod 256) -> rel_err 2.6e-2 == std(b[n]-b[n%256]).
    const float* bias = ((e == 0) ? bias0 : bias1) + n0;
    float* orow = out + ((size_t)e * ROWS_T + r) * OUTD + n0;

    #pragma unroll
    for (int cb = 0; cb < 8; cb++) {                           // 8 x 32 cols
        uint32_t dr[32];
        TC_LD_32X32B_X32(dr, tmem_base + cb * 32);
        TC_WAIT_LD();
        const int c0 = cb * 32;
        #pragma unroll
        for (int j = 0; j < 32; j += 4) {
            float4 v;
            if (tmask) {
                v.x = __uint_as_float(dr[j + 0]) + __ldg(&bias[c0 + j + 0]);
                v.y = __uint_as_float(dr[j + 1]) + __ldg(&bias[c0 + j + 1]);
                v.z = __uint_as_float(dr[j + 2]) + __ldg(&bias[c0 + j + 2]);
                v.w = __uint_as_float(dr[j + 3]) + __ldg(&bias[c0 + j + 3]);
            } else {
                v.x = 0.f; v.y = 0.f; v.z = 0.f; v.w = 0.f;
            }
            *reinterpret_cast<float4*>(orow + c0 + j) = v;
        }
    }
    TC_FENCE_BEFORE();

    __syncthreads();
    if (wid == 0) TC_DEALLOC(tmem_base, 256);
#endif  // TC_PATH
}

// ===================================================================
//       wmma fallback (compiled only when tcgen05 is unavailable)
// ===================================================================
__global__ __launch_bounds__(256, 2)
void motmod_wmma_kernel(const int* __restrict__ type_ids,
                        const float* __restrict__ bias0,
                        const float* __restrict__ bias1,
                        float* __restrict__ out) {
#if !TC_PATH && defined(__CUDA_ARCH__)
    using namespace nvcuda;
    extern __shared__ __align__(16) char fsmem_raw[];
    __half* fsmem = reinterpret_cast<__half*>(fsmem_raw);

    const int tid = threadIdx.x, wid = tid >> 5, lane = tid & 31;
    const int n0 = blockIdx.x * 128;
    const int m0 = blockIdx.y * 128;
    const int e  = blockIdx.z;

    __half* As = fsmem;                        // 2 stages of 128*FB_LD halves
    __half* Bs = fsmem + 2 * FB_TILEH;
    float* staging = reinterpret_cast<float*>(fsmem + 4 * FB_TILEH) + wid * 16 * 20;

    const __half* Ag = g_Xh + (size_t)m0 * DK;
    const __half* Bg = g_Wt + ((size_t)e * OUTD + n0) * DK;

    const uint32_t As_u = smem_u32(As);
    const uint32_t Bs_u = smem_u32(Bs);

    // 512 x 16B vectors per tile (128 rows x 4 chunks); 256 threads -> 2 each
    auto load_tiles = [&](int s, int k0) {
        #pragma unroll
        for (int t = 0; t < 2; t++) {
            int idx = tid + t * 256;           // 0..511
            int row = idx >> 2, c = idx & 3;
            uint32_t off = (uint32_t)((s * FB_TILEH + row * FB_LD + c * 8) * 2);
            cp_async16(As_u + off, Ag + (size_t)row * DK + k0 + c * 8);
            cp_async16(Bs_u + off, Bg + (size_t)row * DK + k0 + c * 8);
        }
        CP_COMMIT();
    };

    wmma::fragment<wmma::accumulator, 16, 16, 16, float> acc[2][4];
    #pragma unroll
    for (int i = 0; i < 2; i++)
        #pragma unroll
        for (int j = 0; j < 4; j++) wmma::fill_fragment(acc[i][j], 0.0f);

    const int wy = wid & 3, wx = wid >> 2;     // warp -> 32(M) x 64(N) subtile
    const int mw = wy * 32, nw = wx * 64;

    load_tiles(0, 0);
    for (int kb = 0; kb < DK / 32; kb++) {
        CP_WAIT0();
        __syncthreads();
        if (kb + 1 < DK / 32) load_tiles((kb + 1) & 1, (kb + 1) * 32);

        const __half* a_base = As + (kb & 1) * FB_TILEH;
        const __half* b_base = Bs + (kb & 1) * FB_TILEH;
        #pragma unroll
        for (int kk = 0; kk < 2; kk++) {
            wmma::fragment<wmma::matrix_a, 16, 16, 16, __half, wmma::row_major> af[2];
            wmma::fragment<wmma::matrix_b, 16, 16, 16, __half, wmma::col_major> bf[4];
            #pragma unroll
            for (int i = 0; i < 2; i++)
                wmma::load_matrix_sync(af[i], a_base + (mw + i * 16) * FB_LD + kk * 16, FB_LD);
            #pragma unroll
            for (int j = 0; j < 4; j++)
                wmma::load_matrix_sync(bf[j], b_base + (nw + j * 16) * FB_LD + kk * 16, FB_LD);
            #pragma unroll
            for (int i = 0; i < 2; i++)
                #pragma unroll
                for (int j = 0; j < 4; j++)
                    wmma::mma_sync(acc[i][j], af[i], bf[j], acc[i][j]);
        }
        __syncthreads();
    }

    const float* bias = (e == 0) ? bias0 : bias1;
    #pragma unroll
    for (int i = 0; i < 2; i++) {
        #pragma unroll
        for (int j = 0; j < 4; j++) {
            wmma::store_matrix_sync(staging, acc[i][j], 20, wmma::mem_row_major);
            __syncwarp();
            const int r  = lane >> 1;
            const int ch = (lane & 1) * 8;
            const int gm = m0 + mw + i * 16 + r;
            const int gn = n0 + nw + j * 16 + ch;
            const bool msk = (type_ids[gm] == e);
            float* op = out + ((size_t)e * ROWS_T + gm) * OUTD + gn;
            float4 v0, v1;
            if (msk) {
                const float* sp = staging + r * 20 + ch;
                v0.x = sp[0] + bias[gn + 0]; v0.y = sp[1] + bias[gn + 1];
                v0.z = sp[2] + bias[gn + 2]; v0.w = sp[3] + bias[gn + 3];
                v1.x = sp[4] + bias[gn + 4]; v1.y = sp[5] + bias[gn + 5];
                v1.z = sp[6] + bias[gn + 6]; v1.w = sp[7] + bias[gn + 7];
            } else {
                v0.x = v0.y = v0.z = v0.w = 0.f;
                v1.x = v1.y = v1.z = v1.w = 0.f;
            }
            *reinterpret_cast<float4*>(op)     = v0;
            *reinterpret_cast<float4*>(op + 4) = v1;
            __syncwarp();
        }
    }
#endif  // !TC_PATH
}

// ---------------- launch ----------------
extern "C" void kernel_launch(void* const* d_in, const int* in_sizes, int n_in,
                              void* d_out, int out_size) {
    (void)in_sizes; (void)n_in; (void)out_size;
    const float* x   = (const float*)d_in[0];
    const int*   tti = (const int*)d_in[1];
    const float* W0  = (const float*)d_in[2];
    const float* b0  = (const float*)d_in[3];
    const float* W1  = (const float*)d_in[4];
    const float* b1  = (const float*)d_in[5];
    float* out = (float*)d_out;

    // fp32 -> fp16 operand prep (needed by both paths)
    conv_x_kernel<<<(ROWS_T * (DK / 4)) / 256, 256>>>(x);
    dim3 wgrid(OUTD / 32, DK / 32);
    conv_w_kernel<<<wgrid, dim3(32, 8)>>>(W0, 0);
    conv_w_kernel<<<wgrid, dim3(32, 8)>>>(W1, 1);

    cudaFuncSetAttribute(motmod_gemm_kernel,
                         cudaFuncAttributeMaxDynamicSharedMemorySize, SMEM_TOTAL);
    cudaFuncSetAttribute(motmod_wmma_kernel,
                         cudaFuncAttributeMaxDynamicSharedMemorySize, FB_SMEM);

    // tcgen05 path (real body only in the sm_103a image; no-op elsewhere)
    dim3 grid_tc(OUTD / NT, ROWS_T / MT, NEXP);                // 16 x 128 x 2
    motmod_gemm_kernel<<<grid_tc, 128, SMEM_TOTAL>>>(tti, b0, b1, out);

    // wmma fallback (real body only in non-accel images; no-op on sm_103a)
    dim3 grid_fb(OUTD / 128, ROWS_T / 128, NEXP);              // 32 x 128 x 2
    motmod_wmma_kernel<<<grid_fb, 256, FB_SMEM>>>(tti, b0, b1, out);
}

// round 12
// speedup vs baseline: 1.0236x; 1.0236x over previous
#include <cuda_runtime.h>
#include <cuda_fp16.h>
#include <mma.h>
#include <cstdint>
#include <cstddef>

// ---------------- arch-conditional path selection ----------------
#if defined(__CUDA_ARCH__) && \
    (defined(__CUDA_ARCH_FEAT_SM103_ALL) || defined(__CUDA_ARCH_FEAT_SM100_ALL) || \
     defined(__CUDA_ARCH_SPECIFIC__) || defined(__CUDA_ARCH_FAMILY_SPECIFIC__))
#define TC_PATH 1
#else
#define TC_PATH 0
#endif

// ---------------- problem dims ----------------
#define ROWS_T 16384   // B*S
#define DK     1024    // d_model (K)
#define OUTD   4096    // out_dim (N total)
#define NEXP   2       // modalities

// ---------------- tcgen05 tiling (R11: 256x256 tile, 3-stage pipeline) ----------------
#define MT 256         // M tile = 2 x M=128 MMA sub-tiles (share B)
#define NT 256         // N tile = 2 x N=128 MMA atoms
#define KC 64          // K chunk (64 halves = 128B SW128 rows)
#define NKC (DK / KC)  // 16
#define ST 3           // pipeline stages (cp.async wait_group 1)

#define STAGE_A_BYTES (MT * 128)            // 32 KB
#define STAGE_B_BYTES (NT * 128)            // 32 KB
#define STAGE_BYTES   (STAGE_A_BYTES + STAGE_B_BYTES)      // 64 KB
#define SMEM_TOTAL    (2048 + ST * STAGE_BYTES)            // 198656 B -> 1 CTA/SM

// idesc kind::f16: dtype=F32 (bit4), atype=btype=F16 (0), N=128 -> 16<<17, M=128 -> 8<<24
#define IDESC_F16 ((1u << 4) | (16u << 17) | (8u << 24))

// ---------------- fallback (wmma) tiling ----------------
#define FB_LD    40
#define FB_TILEH (128 * FB_LD)
#define FB_SMEM  (4 * FB_TILEH * 2 + 8 * 16 * 20 * 4)

// ---------------- scratch (fp16 operands) ----------------
__device__ __half g_Xh[(size_t)ROWS_T * DK];          // X cast to fp16, row-major [ROWS, DK]
__device__ __half g_Wt[(size_t)NEXP * OUTD * DK];     // W transposed to [OUT, DK] K-major, fp16

// ---------------- generic helpers ----------------
__device__ __forceinline__ uint32_t smem_u32(const void* p) {
    uint32_t a;
    asm("{ .reg .u64 t; cvta.to.shared.u64 t, %1; cvt.u32.u64 %0, t; }" : "=r"(a) : "l"(p));
    return a;
}

#define SWZ(o) ((o) ^ (((o) >> 3) & 0x70))

__device__ __forceinline__ void cp_async16(uint32_t dst_smem, const void* src) {
    asm volatile("cp.async.cg.shared.global [%0], [%1], 16;" :: "r"(dst_smem), "l"(src));
}
#define CP_COMMIT() asm volatile("cp.async.commit_group;" ::: "memory")
#define CP_WAIT1()  asm volatile("cp.async.wait_group 1;"  ::: "memory")
#define CP_WAIT0()  asm volatile("cp.async.wait_group 0;"  ::: "memory")

__device__ __forceinline__ void mbar_init(uint32_t mbar, uint32_t count) {
    asm volatile("mbarrier.init.shared.b64 [%0], %1;" :: "r"(mbar), "r"(count) : "memory");
}

__device__ __forceinline__ void mbar_wait(uint32_t mbar, uint32_t parity) {
    asm volatile(
        "{\n\t.reg .pred P;\n"
        "WL_%=:\n\t"
        "mbarrier.try_wait.parity.acquire.cta.shared::cta.b64 P, [%0], %1, 0x989680;\n\t"
        "@P bra.uni WD_%=;\n\t"
        "bra.uni WL_%=;\n"
        "WD_%=:\n\t}"
        :: "r"(mbar), "r"(parity) : "memory");
}

// ---------------- conversion kernels ----------------
__global__ void conv_x_kernel(const float* __restrict__ x) {
    size_t i = (size_t)blockIdx.x * blockDim.x + threadIdx.x;
    float4 v = reinterpret_cast<const float4*>(x)[i];
    __half2* o = reinterpret_cast<__half2*>(g_Xh);
    o[i * 2 + 0] = __floats2half2_rn(v.x, v.y);
    o[i * 2 + 1] = __floats2half2_rn(v.z, v.w);
}

// W [DK, OUTD] fp32 row-major  ->  g_Wt[e] [OUTD, DK] fp16 K-major (transpose + cast)
__global__ void conv_w_kernel(const float* __restrict__ W, int e) {
    __shared__ float t[32][33];
    int o0 = blockIdx.x * 32, d0 = blockIdx.y * 32;
    int tx = threadIdx.x, ty = threadIdx.y;   // (32, 8)
    #pragma unroll
    for (int j = 0; j < 32; j += 8)
        t[ty + j][tx] = W[(size_t)(d0 + ty + j) * OUTD + o0 + tx];
    __syncthreads();
    __half* Wt = g_Wt + (size_t)e * OUTD * DK;
    #pragma unroll
    for (int j = 0; j < 32; j += 8)
        Wt[(size_t)(o0 + ty + j) * DK + d0 + tx] = __float2half(t[tx][ty + j]);
}

// ===================================================================
//                    tcgen05 path (sm_103a only)
// ===================================================================
#if TC_PATH
__device__ __forceinline__ uint64_t make_desc_sw128(uint32_t addr) {
    // layout=SW128(2), version=1 (Blackwell), SBO=64 (1024B per 8-row group), LBO=1 (16B)
    const uint64_t base = (uint64_t(2) << 61) | (uint64_t(1) << 46) |
                          (uint64_t(64) << 32) | (uint64_t(1) << 16);
    return base | ((uint64_t)(addr >> 4) & 0x3FFF);
}

__device__ __forceinline__ void tcgen05_mma_f16_ss(uint32_t d_tmem, uint64_t a_desc,
                                                   uint64_t b_desc, uint32_t idesc,
                                                   uint32_t enable_d) {
    asm volatile(
        "{\n\t.reg .pred p;\n\t"
        "setp.ne.u32 p, %5, 0;\n\t"
        "tcgen05.mma.cta_group::1.kind::f16 [%0], %1, %2, %3, {%4, %4, %4, %4}, p;\n\t}"
        :: "r"(d_tmem), "l"(a_desc), "l"(b_desc), "r"(idesc), "r"(0u), "r"(enable_d)
        : "memory");
}

#define TC_COMMIT(mbar) \
    asm volatile("tcgen05.commit.cta_group::1.mbarrier::arrive::one.shared::cluster.b64 [%0];" \
                 :: "r"(mbar) : "memory")
#define TC_ALLOC(dst_smem, ncols) \
    asm volatile("tcgen05.alloc.cta_group::1.sync.aligned.shared::cta.b32 [%0], %1;" \
                 :: "r"(dst_smem), "r"(ncols) : "memory")
#define TC_DEALLOC(tmem, ncols) \
    asm volatile("tcgen05.dealloc.cta_group::1.sync.aligned.b32 %0, %1;" :: "r"(tmem), "r"(ncols))
#define TC_RELINQ() \
    asm volatile("tcgen05.relinquish_alloc_permit.cta_group::1.sync.aligned;")
#define TC_FENCE_AFTER()  asm volatile("tcgen05.fence::after_thread_sync;" ::: "memory")
#define TC_FENCE_BEFORE() asm volatile("tcgen05.fence::before_thread_sync;" ::: "memory")
#define TC_WAIT_LD()      asm volatile("tcgen05.wait::ld.sync.aligned;" ::: "memory")
#define FENCE_PROXY_ASYNC() asm volatile("fence.proxy.async.shared::cta;" ::: "memory")

#define TC_LD_32X32B_X32(r, tmem_addr) \
    asm volatile( \
        "tcgen05.ld.sync.aligned.32x32b.x32.b32 " \
        "{%0, %1, %2, %3, %4, %5, %6, %7, " \
        " %8, %9, %10, %11, %12, %13, %14, %15, " \
        " %16, %17, %18, %19, %20, %21, %22, %23, " \
        " %24, %25, %26, %27, %28, %29, %30, %31}, [%32];" \
        : "=r"((r)[0]),  "=r"((r)[1]),  "=r"((r)[2]),  "=r"((r)[3]), \
          "=r"((r)[4]),  "=r"((r)[5]),  "=r"((r)[6]),  "=r"((r)[7]), \
          "=r"((r)[8]),  "=r"((r)[9]),  "=r"((r)[10]), "=r"((r)[11]), \
          "=r"((r)[12]), "=r"((r)[13]), "=r"((r)[14]), "=r"((r)[15]), \
          "=r"((r)[16]), "=r"((r)[17]), "=r"((r)[18]), "=r"((r)[19]), \
          "=r"((r)[20]), "=r"((r)[21]), "=r"((r)[22]), "=r"((r)[23]), \
          "=r"((r)[24]), "=r"((r)[25]), "=r"((r)[26]), "=r"((r)[27]), \
          "=r"((r)[28]), "=r"((r)[29]), "=r"((r)[30]), "=r"((r)[31]) \
        : "r"(tmem_addr))

// Load one 64KB stage: A 256 rows x 128B + B 256 rows x 128B (SW128 swizzled).
// 256 threads x 16 x cp.async16. Caller commits the group.
__device__ __forceinline__ void load_stage(int tid, uint32_t data_base, int stage, int kc,
                                           const __half* Asrc, const __half* Bsrc) {
    const uint32_t aBase = data_base + (uint32_t)stage * STAGE_BYTES;
    const uint32_t bBase = aBase + STAGE_A_BYTES;
    const int k0 = kc * KC;
    // A: 256 rows x 8 x 16B chunks = 2048 vectors
    #pragma unroll
    for (int t = 0; t < 8; t++) {
        int idx = tid + t * 256;          // 0..2047
        int row = idx >> 3, c = idx & 7;
        const __half* src = Asrc + (size_t)row * DK + k0 + c * 8;
        uint32_t off = (uint32_t)(row * 128 + c * 16);
        cp_async16(aBase + SWZ(off), src);
    }
    // B: 256 rows x 8 chunks = 2048 vectors
    #pragma unroll
    for (int t = 0; t < 8; t++) {
        int idx = tid + t * 256;
        int row = idx >> 3, c = idx & 7;
        const __half* src = Bsrc + (size_t)row * DK + k0 + c * 8;
        uint32_t off = (uint32_t)(row * 128 + c * 16);
        cp_async16(bBase + SWZ(off), src);
    }
}
#endif  // TC_PATH

__global__ __launch_bounds__(256, 1)
void motmod_gemm_kernel(const int* __restrict__ type_ids,
                        const float* __restrict__ bias0,
                        const float* __restrict__ bias1,
                        float* __restrict__ out) {
#if TC_PATH
    extern __shared__ __align__(16) char smem[];
    const uint32_t smem_base = smem_u32(smem);
    const uint32_t data_base = (smem_base + 1024u + 1023u) & ~1023u;   // 1024B-aligned tiles
    const int tid = threadIdx.x;
    const int wid = tid >> 5, lid = tid & 31;

    const int n0 = blockIdx.x * NT;
    const int m0 = blockIdx.y * MT;
    const int e  = blockIdx.z;

    const uint32_t mbar0 = smem_base + 16;          // ST mbarriers, 8B each

    if (wid == 0) {
        TC_ALLOC(smem_base, 512);                   // full TMEM: 2 M-subtiles x 256 cols
        TC_RELINQ();
    }
    if (tid == 0) {
        #pragma unroll
        for (int s = 0; s < ST; s++) mbar_init(mbar0 + s * 8, 1);
    }
    __syncthreads();

    uint32_t tmem_base;
    asm volatile("ld.shared.b32 %0, [%1];" : "=r"(tmem_base) : "r"(smem_base));

    const __half* Asrc = g_Xh + (size_t)m0 * DK;
    const __half* Bsrc = g_Wt + ((size_t)e * OUTD + n0) * DK;

    // prologue: stages 0 and 1 in flight (one commit group each)
    load_stage(tid, data_base, 0, 0, Asrc, Bsrc);
    CP_COMMIT();
    load_stage(tid, data_base, 1, 1, Asrc, Bsrc);
    CP_COMMIT();

    for (int i = 0; i < NKC; i++) {
        const int b = i % ST;
        CP_WAIT1();                     // all but the newest group done -> stage i ready
        __syncthreads();

        if (tid == 0) {
            FENCE_PROXY_ASYNC();
            const uint32_t aBase = data_base + (uint32_t)b * STAGE_BYTES;
            const uint32_t bBase = aBase + STAGE_A_BYTES;
            const uint64_t ad = make_desc_sw128(aBase);
            const uint64_t bd = make_desc_sw128(bBase);
            #pragma unroll
            for (int ks = 0; ks < 4; ks++) {                  // K=16 per MMA
                const uint32_t acc = (i > 0 || ks > 0) ? 1u : 0u;
                #pragma unroll
                for (int mt = 0; mt < 2; mt++) {              // two M=128 sub-tiles
                    #pragma unroll
                    for (int h = 0; h < 2; h++) {             // two N=128 halves
                        tcgen05_mma_f16_ss(tmem_base + mt * 256 + h * 128,
                                           ad + (uint64_t)mt * 1024 + ks * 2,
                                           bd + (uint64_t)h  * 1024 + ks * 2,
                                           IDESC_F16, acc);
                    }
                }
            }
            TC_COMMIT(mbar0 + b * 8);
        }

        const int ld = i + (ST - 1);
        const int w  = ld - ST;                       // chunk that last used buffer ld%ST
        if (w >= 0) mbar_wait(mbar0 + (w % ST) * 8, (w / ST) & 1);
        if (ld < NKC) load_stage(tid, data_base, ld % ST, ld, Asrc, Bsrc);
        CP_COMMIT();                                  // empty group in the tail keeps
                                                      // wait_group 1 semantics exact
    }

    // wait for the final chunk's MMAs
    {
        const int w = NKC - 1;
        mbar_wait(mbar0 + (w % ST) * 8, (w / ST) & 1);
    }
    TC_FENCE_AFTER();

    // ---------------- epilogue: LDTM + mask + bias + store ----------------
    // warps 0-3: M-subtile 0 (TMEM cols [0,256));  warps 4-7: M-subtile 1 (cols [256,512))
    const int mt   = wid >> 2;
    const int wsub = wid & 3;
    const int r = m0 + mt * 128 + wsub * 32 + lid;             // global token row
    const int tmask = (type_ids[r] == e);
    const float* bias = ((e == 0) ? bias0 : bias1) + n0;
    float* orow = out + ((size_t)e * ROWS_T + r) * OUTD + n0;
    const uint32_t treg = tmem_base + mt * 256;

    #pragma unroll
    for (int cb = 0; cb < 8; cb++) {                           // 8 x 32 cols
        uint32_t dr[32];
        TC_LD_32X32B_X32(dr, treg + cb * 32);
        TC_WAIT_LD();
        const int c0 = cb * 32;
        #pragma unroll
        for (int j = 0; j < 32; j += 4) {
            float4 v;
            if (tmask) {
                v.x = __uint_as_float(dr[j + 0]) + __ldg(&bias[c0 + j + 0]);
                v.y = __uint_as_float(dr[j + 1]) + __ldg(&bias[c0 + j + 1]);
                v.z = __uint_as_float(dr[j + 2]) + __ldg(&bias[c0 + j + 2]);
                v.w = __uint_as_float(dr[j + 3]) + __ldg(&bias[c0 + j + 3]);
            } else {
                v.x = 0.f; v.y = 0.f; v.z = 0.f; v.w = 0.f;
            }
            *reinterpret_cast<float4*>(orow + c0 + j) = v;
        }
    }
    TC_FENCE_BEFORE();

    __syncthreads();
    if (wid == 0) TC_DEALLOC(tmem_base, 512);
#endif  // TC_PATH
}

// ===================================================================
//       wmma fallback (compiled only when tcgen05 is unavailable)
// ===================================================================
__global__ __launch_bounds__(256, 2)
void motmod_wmma_kernel(const int* __restrict__ type_ids,
                        const float* __restrict__ bias0,
                        const float* __restrict__ bias1,
                        float* __restrict__ out) {
#if !TC_PATH && defined(__CUDA_ARCH__)
    using namespace nvcuda;
    extern __shared__ __align__(16) char fsmem_raw[];
    __half* fsmem = reinterpret_cast<__half*>(fsmem_raw);

    const int tid = threadIdx.x, wid = tid >> 5, lane = tid & 31;
    const int n0 = blockIdx.x * 128;
    const int m0 = blockIdx.y * 128;
    const int e  = blockIdx.z;

    __half* As = fsmem;
    __half* Bs = fsmem + 2 * FB_TILEH;
    float* staging = reinterpret_cast<float*>(fsmem + 4 * FB_TILEH) + wid * 16 * 20;

    const __half* Ag = g_Xh + (size_t)m0 * DK;
    const __half* Bg = g_Wt + ((size_t)e * OUTD + n0) * DK;

    const uint32_t As_u = smem_u32(As);
    const uint32_t Bs_u = smem_u32(Bs);

    auto load_tiles = [&](int s, int k0) {
        #pragma unroll
        for (int t = 0; t < 2; t++) {
            int idx = tid + t * 256;
            int row = idx >> 2, c = idx & 3;
            uint32_t off = (uint32_t)((s * FB_TILEH + row * FB_LD + c * 8) * 2);
            cp_async16(As_u + off, Ag + (size_t)row * DK + k0 + c * 8);
            cp_async16(Bs_u + off, Bg + (size_t)row * DK + k0 + c * 8);
        }
        CP_COMMIT();
    };

    wmma::fragment<wmma::accumulator, 16, 16, 16, float> acc[2][4];
    #pragma unroll
    for (int i = 0; i < 2; i++)
        #pragma unroll
        for (int j = 0; j < 4; j++) wmma::fill_fragment(acc[i][j], 0.0f);

    const int wy = wid & 3, wx = wid >> 2;
    const int mw = wy * 32, nw = wx * 64;

    load_tiles(0, 0);
    for (int kb = 0; kb < DK / 32; kb++) {
        CP_WAIT0();
        __syncthreads();
        if (kb + 1 < DK / 32) load_tiles((kb + 1) & 1, (kb + 1) * 32);

        const __half* a_base = As + (kb & 1) * FB_TILEH;
        const __half* b_base = Bs + (kb & 1) * FB_TILEH;
        #pragma unroll
        for (int kk = 0; kk < 2; kk++) {
            wmma::fragment<wmma::matrix_a, 16, 16, 16, __half, wmma::row_major> af[2];
            wmma::fragment<wmma::matrix_b, 16, 16, 16, __half, wmma::col_major> bf[4];
            #pragma unroll
            for (int i = 0; i < 2; i++)
                wmma::load_matrix_sync(af[i], a_base + (mw + i * 16) * FB_LD + kk * 16, FB_LD);
            #pragma unroll
            for (int j = 0; j < 4; j++)
                wmma::load_matrix_sync(bf[j], b_base + (nw + j * 16) * FB_LD + kk * 16, FB_LD);
            #pragma unroll
            for (int i = 0; i < 2; i++)
                #pragma unroll
                for (int j = 0; j < 4; j++)
                    wmma::mma_sync(acc[i][j], af[i], bf[j], acc[i][j]);
        }
        __syncthreads();
    }

    const float* bias = (e == 0) ? bias0 : bias1;
    #pragma unroll
    for (int i = 0; i < 2; i++) {
        #pragma unroll
        for (int j = 0; j < 4; j++) {
            wmma::store_matrix_sync(staging, acc[i][j], 20, wmma::mem_row_major);
            __syncwarp();
            const int r  = lane >> 1;
            const int ch = (lane & 1) * 8;
            const int gm = m0 + mw + i * 16 + r;
            const int gn = n0 + nw + j * 16 + ch;
            const bool msk = (type_ids[gm] == e);
            float* op = out + ((size_t)e * ROWS_T + gm) * OUTD + gn;
            float4 v0, v1;
            if (msk) {
                const float* sp = staging + r * 20 + ch;
                v0.x = sp[0] + bias[gn + 0]; v0.y = sp[1] + bias[gn + 1];
                v0.z = sp[2] + bias[gn + 2]; v0.w = sp[3] + bias[gn + 3];
                v1.x = sp[4] + bias[gn + 4]; v1.y = sp[5] + bias[gn + 5];
                v1.z = sp[6] + bias[gn + 6]; v1.w = sp[7] + bias[gn + 7];
            } else {
                v0.x = v0.y = v0.z = v0.w = 0.f;
                v1.x = v1.y = v1.z = v1.w = 0.f;
            }
            *reinterpret_cast<float4*>(op)     = v0;
            *reinterpret_cast<float4*>(op + 4) = v1;
            __syncwarp();
        }
    }
#endif  // !TC_PATH
}

// ---------------- launch ----------------
extern "C" void kernel_launch(void* const* d_in, const int* in_sizes, int n_in,
                              void* d_out, int out_size) {
    (void)in_sizes; (void)n_in; (void)out_size;
    const float* x   = (const float*)d_in[0];
    const int*   tti = (const int*)d_in[1];
    const float* W0  = (const float*)d_in[2];
    const float* b0  = (const float*)d_in[3];
    const float* W1  = (const float*)d_in[4];
    const float* b1  = (const float*)d_in[5];
    float* out = (float*)d_out;

    // fp32 -> fp16 operand prep (needed by both paths)
    conv_x_kernel<<<(ROWS_T * (DK / 4)) / 256, 256>>>(x);
    dim3 wgrid(OUTD / 32, DK / 32);
    conv_w_kernel<<<wgrid, dim3(32, 8)>>>(W0, 0);
    conv_w_kernel<<<wgrid, dim3(32, 8)>>>(W1, 1);

    cudaFuncSetAttribute(motmod_gemm_kernel,
                         cudaFuncAttributeMaxDynamicSharedMemorySize, SMEM_TOTAL);
    cudaFuncSetAttribute(motmod_wmma_kernel,
                         cudaFuncAttributeMaxDynamicSharedMemorySize, FB_SMEM);

    // tcgen05 path (real body only in the sm_103a image; no-op elsewhere)
    dim3 grid_tc(OUTD / NT, ROWS_T / MT, NEXP);                // 16 x 64 x 2 = 2048 CTAs
    motmod_gemm_kernel<<<grid_tc, 256, SMEM_TOTAL>>>(tti, b0, b1, out);

    // wmma fallback (real body only in non-accel images; no-op on sm_103a)
    dim3 grid_fb(OUTD / 128, ROWS_T / 128, NEXP);
    motmod_wmma_kernel<<<grid_fb, 256, FB_SMEM>>>(tti, b0, b1, out);
}

// round 15
// speedup vs baseline: 1.0445x; 1.0205x over previous
#include <cuda_runtime.h>
#include <cuda_fp16.h>
#include <mma.h>
#include <cstdint>
#include <cstddef>

// ---------------- arch-conditional path selection ----------------
#if defined(__CUDA_ARCH__) && \
    (defined(__CUDA_ARCH_FEAT_SM103_ALL) || defined(__CUDA_ARCH_FEAT_SM100_ALL) || \
     defined(__CUDA_ARCH_SPECIFIC__) || defined(__CUDA_ARCH_FAMILY_SPECIFIC__))
#define TC_PATH 1
#else
#define TC_PATH 0
#endif

// ---------------- problem dims ----------------
#define ROWS_T 16384   // B*S
#define DK     1024    // d_model (K)
#define OUTD   4096    // out_dim (N total)
#define NEXP   2       // modalities

// ---------------- tcgen05 tiling (R13: warp-specialized producer/consumer) ----------------
#define MT 256         // M tile = 2 x M=128 MMA sub-tiles (share B)
#define NT 256         // N tile = 2 x N=128 MMA atoms
#define KC 64          // K chunk (64 halves = 128B SW128 rows)
#define NKC (DK / KC)  // 16
#define ST 3           // pipeline stages

#define STAGE_A_BYTES (MT * 128)            // 32 KB
#define STAGE_B_BYTES (NT * 128)            // 32 KB
#define STAGE_BYTES   (STAGE_A_BYTES + STAGE_B_BYTES)      // 64 KB
#define SMEM_TOTAL    (2048 + ST * STAGE_BYTES)            // 198656 B -> 1 CTA/SM

// idesc kind::f16: dtype=F32 (bit4), atype=btype=F16 (0), N=128 -> 16<<17, M=128 -> 8<<24
#define IDESC_F16 ((1u << 4) | (16u << 17) | (8u << 24))

// ---------------- fallback (wmma) tiling ----------------
#define FB_LD    40
#define FB_TILEH (128 * FB_LD)
#define FB_SMEM  (4 * FB_TILEH * 2 + 8 * 16 * 20 * 4)

// ---------------- scratch (fp16 operands) ----------------
__device__ __half g_Xh[(size_t)ROWS_T * DK];          // X cast to fp16, row-major [ROWS, DK]
__device__ __half g_Wt[(size_t)NEXP * OUTD * DK];     // W transposed to [OUT, DK] K-major, fp16

// ---------------- generic helpers ----------------
__device__ __forceinline__ uint32_t smem_u32(const void* p) {
    uint32_t a;
    asm("{ .reg .u64 t; cvta.to.shared.u64 t, %1; cvt.u32.u64 %0, t; }" : "=r"(a) : "l"(p));
    return a;
}

#define SWZ(o) ((o) ^ (((o) >> 3) & 0x70))

__device__ __forceinline__ void cp_async16(uint32_t dst_smem, const void* src) {
    asm volatile("cp.async.cg.shared.global [%0], [%1], 16;" :: "r"(dst_smem), "l"(src));
}
#define CP_COMMIT() asm volatile("cp.async.commit_group;" ::: "memory")
#define CP_WAIT0()  asm volatile("cp.async.wait_group 0;"  ::: "memory")

// arrive on mbarrier when ALL prior cp.async of this thread have completed;
// .noinc: counts against the pre-initialized expected-arrival count.
__device__ __forceinline__ void cpasync_mbar_arrive_noinc(uint32_t mbar) {
    asm volatile("cp.async.mbarrier.arrive.noinc.shared::cta.b64 [%0];" :: "r"(mbar) : "memory");
}

__device__ __forceinline__ void mbar_init(uint32_t mbar, uint32_t count) {
    asm volatile("mbarrier.init.shared.b64 [%0], %1;" :: "r"(mbar), "r"(count) : "memory");
}

__device__ __forceinline__ void mbar_wait(uint32_t mbar, uint32_t parity) {
    asm volatile(
        "{\n\t.reg .pred P;\n"
        "WL_%=:\n\t"
        "mbarrier.try_wait.parity.acquire.cta.shared::cta.b64 P, [%0], %1, 0x989680;\n\t"
        "@P bra.uni WD_%=;\n\t"
        "bra.uni WL_%=;\n"
        "WD_%=:\n\t}"
        :: "r"(mbar), "r"(parity) : "memory");
}

// ---------------- conversion kernels ----------------
__global__ void conv_x_kernel(const float* __restrict__ x) {
    size_t i = (size_t)blockIdx.x * blockDim.x + threadIdx.x;
    float4 v = reinterpret_cast<const float4*>(x)[i];
    __half2* o = reinterpret_cast<__half2*>(g_Xh);
    o[i * 2 + 0] = __floats2half2_rn(v.x, v.y);
    o[i * 2 + 1] = __floats2half2_rn(v.z, v.w);
}

// W [DK, OUTD] fp32 row-major  ->  g_Wt[e] [OUTD, DK] fp16 K-major (transpose + cast)
__global__ void conv_w_kernel(const float* __restrict__ W, int e) {
    __shared__ float t[32][33];
    int o0 = blockIdx.x * 32, d0 = blockIdx.y * 32;
    int tx = threadIdx.x, ty = threadIdx.y;   // (32, 8)
    #pragma unroll
    for (int j = 0; j < 32; j += 8)
        t[ty + j][tx] = W[(size_t)(d0 + ty + j) * OUTD + o0 + tx];
    __syncthreads();
    __half* Wt = g_Wt + (size_t)e * OUTD * DK;
    #pragma unroll
    for (int j = 0; j < 32; j += 8)
        Wt[(size_t)(o0 + ty + j) * DK + d0 + tx] = __float2half(t[tx][ty + j]);
}

// ===================================================================
//                    tcgen05 path (sm_103a only)
// ===================================================================
#if TC_PATH
__device__ __forceinline__ uint64_t make_desc_sw128(uint32_t addr) {
    // layout=SW128(2), version=1 (Blackwell), SBO=64 (1024B per 8-row group), LBO=1 (16B)
    const uint64_t base = (uint64_t(2) << 61) | (uint64_t(1) << 46) |
                          (uint64_t(64) << 32) | (uint64_t(1) << 16);
    return base | ((uint64_t)(addr >> 4) & 0x3FFF);
}

__device__ __forceinline__ void tcgen05_mma_f16_ss(uint32_t d_tmem, uint64_t a_desc,
                                                   uint64_t b_desc, uint32_t idesc,
                                                   uint32_t enable_d) {
    asm volatile(
        "{\n\t.reg .pred p;\n\t"
        "setp.ne.u32 p, %5, 0;\n\t"
        "tcgen05.mma.cta_group::1.kind::f16 [%0], %1, %2, %3, {%4, %4, %4, %4}, p;\n\t}"
        :: "r"(d_tmem), "l"(a_desc), "l"(b_desc), "r"(idesc), "r"(0u), "r"(enable_d)
        : "memory");
}

#define TC_COMMIT(mbar) \
    asm volatile("tcgen05.commit.cta_group::1.mbarrier::arrive::one.shared::cluster.b64 [%0];" \
                 :: "r"(mbar) : "memory")
#define TC_ALLOC(dst_smem, ncols) \
    asm volatile("tcgen05.alloc.cta_group::1.sync.aligned.shared::cta.b32 [%0], %1;" \
                 :: "r"(dst_smem), "r"(ncols) : "memory")
#define TC_DEALLOC(tmem, ncols) \
    asm volatile("tcgen05.dealloc.cta_group::1.sync.aligned.b32 %0, %1;" :: "r"(tmem), "r"(ncols))
#define TC_RELINQ() \
    asm volatile("tcgen05.relinquish_alloc_permit.cta_group::1.sync.aligned;")
#define TC_FENCE_AFTER()  asm volatile("tcgen05.fence::after_thread_sync;" ::: "memory")
#define TC_FENCE_BEFORE() asm volatile("tcgen05.fence::before_thread_sync;" ::: "memory")
#define TC_WAIT_LD()      asm volatile("tcgen05.wait::ld.sync.aligned;" ::: "memory")
#define FENCE_PROXY_ASYNC() asm volatile("fence.proxy.async.shared::cta;" ::: "memory")

#define TC_LD_32X32B_X32(r, tmem_addr) \
    asm volatile( \
        "tcgen05.ld.sync.aligned.32x32b.x32.b32 " \
        "{%0, %1, %2, %3, %4, %5, %6, %7, " \
        " %8, %9, %10, %11, %12, %13, %14, %15, " \
        " %16, %17, %18, %19, %20, %21, %22, %23, " \
        " %24, %25, %26, %27, %28, %29, %30, %31}, [%32];" \
        : "=r"((r)[0]),  "=r"((r)[1]),  "=r"((r)[2]),  "=r"((r)[3]), \
          "=r"((r)[4]),  "=r"((r)[5]),  "=r"((r)[6]),  "=r"((r)[7]), \
          "=r"((r)[8]),  "=r"((r)[9]),  "=r"((r)[10]), "=r"((r)[11]), \
          "=r"((r)[12]), "=r"((r)[13]), "=r"((r)[14]), "=r"((r)[15]), \
          "=r"((r)[16]), "=r"((r)[17]), "=r"((r)[18]), "=r"((r)[19]), \
          "=r"((r)[20]), "=r"((r)[21]), "=r"((r)[22]), "=r"((r)[23]), \
          "=r"((r)[24]), "=r"((r)[25]), "=r"((r)[26]), "=r"((r)[27]), \
          "=r"((r)[28]), "=r"((r)[29]), "=r"((r)[30]), "=r"((r)[31]) \
        : "r"(tmem_addr))
#endif  // TC_PATH

// smem control block layout (offsets from smem_base):
//   +0   : TMEM base pointer (written by tcgen05.alloc)
//   +16  : full[0..2]   (8B each)  -- producers -> MMA warp (count 128, cp.async tracked)
//   +48  : empty[0..2]  (8B each)  -- MMA commit -> producers (count 1)
//   +80  : done         (8B)       -- final MMA commit -> everyone (count 1)
#define MB_FULL(s)  (smem_base + 16 + (s) * 8)
#define MB_EMPTY(s) (smem_base + 48 + (s) * 8)
#define MB_DONE     (smem_base + 80)

__global__ __launch_bounds__(256, 1)
void motmod_gemm_kernel(const int* __restrict__ type_ids,
                        const float* __restrict__ bias0,
                        const float* __restrict__ bias1,
                        float* __restrict__ out) {
#if TC_PATH
    extern __shared__ __align__(16) char smem[];
    const uint32_t smem_base = smem_u32(smem);
    const uint32_t data_base = (smem_base + 1024u + 1023u) & ~1023u;   // 1024B-aligned tiles
    const int tid = threadIdx.x;
    const int wid = tid >> 5, lid = tid & 31;

    const int n0 = blockIdx.x * NT;
    const int m0 = blockIdx.y * MT;
    const int e  = blockIdx.z;

    if (wid == 0) {
        TC_ALLOC(smem_base, 512);                   // 2 M-subtiles x 256 TMEM cols
        TC_RELINQ();
    }
    if (tid == 0) {
        #pragma unroll
        for (int s = 0; s < ST; s++) {
            mbar_init(MB_FULL(s), 128);             // 128 producer threads
            mbar_init(MB_EMPTY(s), 1);              // one tcgen05.commit
        }
        mbar_init(MB_DONE, 1);
    }
    __syncthreads();

    uint32_t tmem_base;
    asm volatile("ld.shared.b32 %0, [%1];" : "=r"(tmem_base) : "r"(smem_base));

    const __half* Asrc = g_Xh + (size_t)m0 * DK;
    const __half* Bsrc = g_Wt + ((size_t)e * OUTD + n0) * DK;

    if (tid >= 128) {
        // ---------------- producer: warps 4-7, free-running ----------------
        const int p = tid - 128;                    // 0..127
        for (int c = 0; c < NKC; c++) {
            const int s = c % ST;
            if (c >= ST) mbar_wait(MB_EMPTY(s), ((c / ST) - 1) & 1);
            const uint32_t aBase = data_base + (uint32_t)s * STAGE_BYTES;
            const uint32_t bBase = aBase + STAGE_A_BYTES;
            const int k0 = c * KC;
            // A: 256 rows x 8 x 16B = 2048 vectors, 16 per thread
            #pragma unroll
            for (int t = 0; t < 16; t++) {
                int idx = p + t * 128;
                int row = idx >> 3, ch = idx & 7;
                cp_async16(aBase + SWZ((uint32_t)(row * 128 + ch * 16)),
                           Asrc + (size_t)row * DK + k0 + ch * 8);
            }
            // B: 256 rows x 8 x 16B = 2048 vectors, 16 per thread
            #pragma unroll
            for (int t = 0; t < 16; t++) {
                int idx = p + t * 128;
                int row = idx >> 3, ch = idx & 7;
                cp_async16(bBase + SWZ((uint32_t)(row * 128 + ch * 16)),
                           Bsrc + (size_t)row * DK + k0 + ch * 8);
            }
            cpasync_mbar_arrive_noinc(MB_FULL(s));  // arrive when the above complete
        }
    } else if (wid == 0 && lid == 0) {
        // ---------------- MMA issuer: single thread, free-running ----------------
        for (int c = 0; c < NKC; c++) {
            const int s = c % ST;
            mbar_wait(MB_FULL(s), (c / ST) & 1);
            FENCE_PROXY_ASYNC();                    // order producers' smem writes
            const uint32_t aBase = data_base + (uint32_t)s * STAGE_BYTES;
            const uint32_t bBase = aBase + STAGE_A_BYTES;
            const uint64_t ad = make_desc_sw128(aBase);
            const uint64_t bd = make_desc_sw128(bBase);
            #pragma unroll
            for (int ks = 0; ks < 4; ks++) {                  // K=16 per MMA
                const uint32_t acc = (c > 0 || ks > 0) ? 1u : 0u;
                #pragma unroll
                for (int mt = 0; mt < 2; mt++) {              // two M=128 sub-tiles
                    #pragma unroll
                    for (int h = 0; h < 2; h++) {             // two N=128 halves
                        tcgen05_mma_f16_ss(tmem_base + mt * 256 + h * 128,
                                           ad + (uint64_t)mt * 1024 + ks * 2,
                                           bd + (uint64_t)h  * 1024 + ks * 2,
                                           IDESC_F16, acc);
                    }
                }
            }
            TC_COMMIT(MB_EMPTY(s));                 // frees stage s when MMAs drain
        }
        TC_COMMIT(MB_DONE);                         // fires when ALL prior MMAs complete
    }

    // ---------------- epilogue: all 8 warps ----------------
    mbar_wait(MB_DONE, 0);
    TC_FENCE_AFTER();

    // warps 0-3: M-subtile 0 (TMEM cols [0,256)); warps 4-7: M-subtile 1 (cols [256,512))
    const int mt   = wid >> 2;
    const int wsub = wid & 3;
    const int r = m0 + mt * 128 + wsub * 32 + lid;             // global token row
    const int tmask = (type_ids[r] == e);
    const float* bias = ((e == 0) ? bias0 : bias1) + n0;
    float* orow = out + ((size_t)e * ROWS_T + r) * OUTD + n0;
    const uint32_t treg = tmem_base + mt * 256;

    #pragma unroll
    for (int cb = 0; cb < 8; cb++) {                           // 8 x 32 cols
        uint32_t dr[32];
        TC_LD_32X32B_X32(dr, treg + cb * 32);
        TC_WAIT_LD();
        const int c0 = cb * 32;
        #pragma unroll
        for (int j = 0; j < 32; j += 4) {
            float4 v;
            if (tmask) {
                v.x = __uint_as_float(dr[j + 0]) + __ldg(&bias[c0 + j + 0]);
                v.y = __uint_as_float(dr[j + 1]) + __ldg(&bias[c0 + j + 1]);
                v.z = __uint_as_float(dr[j + 2]) + __ldg(&bias[c0 + j + 2]);
                v.w = __uint_as_float(dr[j + 3]) + __ldg(&bias[c0 + j + 3]);
            } else {
                v.x = 0.f; v.y = 0.f; v.z = 0.f; v.w = 0.f;
            }
            *reinterpret_cast<float4*>(orow + c0 + j) = v;
        }
    }
    TC_FENCE_BEFORE();

    __syncthreads();
    if (wid == 0) TC_DEALLOC(tmem_base, 512);
#endif  // TC_PATH
}

// ===================================================================
//       wmma fallback (compiled only when tcgen05 is unavailable)
// ===================================================================
__global__ __launch_bounds__(256, 2)
void motmod_wmma_kernel(const int* __restrict__ type_ids,
                        const float* __restrict__ bias0,
                        const float* __restrict__ bias1,
                        float* __restrict__ out) {
#if !TC_PATH && defined(__CUDA_ARCH__)
    using namespace nvcuda;
    extern __shared__ __align__(16) char fsmem_raw[];
    __half* fsmem = reinterpret_cast<__half*>(fsmem_raw);

    const int tid = threadIdx.x, wid = tid >> 5, lane = tid & 31;
    const int n0 = blockIdx.x * 128;
    const int m0 = blockIdx.y * 128;
    const int e  = blockIdx.z;

    __half* As = fsmem;
    __half* Bs = fsmem + 2 * FB_TILEH;
    float* staging = reinterpret_cast<float*>(fsmem + 4 * FB_TILEH) + wid * 16 * 20;

    const __half* Ag = g_Xh + (size_t)m0 * DK;
    const __half* Bg = g_Wt + ((size_t)e * OUTD + n0) * DK;

    const uint32_t As_u = smem_u32(As);
    const uint32_t Bs_u = smem_u32(Bs);

    auto load_tiles = [&](int s, int k0) {
        #pragma unroll
        for (int t = 0; t < 2; t++) {
            int idx = tid + t * 256;
            int row = idx >> 2, c = idx & 3;
            uint32_t off = (uint32_t)((s * FB_TILEH + row * FB_LD + c * 8) * 2);
            cp_async16(As_u + off, Ag + (size_t)row * DK + k0 + c * 8);
            cp_async16(Bs_u + off, Bg + (size_t)row * DK + k0 + c * 8);
        }
        CP_COMMIT();
    };

    wmma::fragment<wmma::accumulator, 16, 16, 16, float> acc[2][4];
    #pragma unroll
    for (int i = 0; i < 2; i++)
        #pragma unroll
        for (int j = 0; j < 4; j++) wmma::fill_fragment(acc[i][j], 0.0f);

    const int wy = wid & 3, wx = wid >> 2;
    const int mw = wy * 32, nw = wx * 64;

    load_tiles(0, 0);
    for (int kb = 0; kb < DK / 32; kb++) {
        CP_WAIT0();
        __syncthreads();
        if (kb + 1 < DK / 32) load_tiles((kb + 1) & 1, (kb + 1) * 32);

        const __half* a_base = As + (kb & 1) * FB_TILEH;
        const __half* b_base = Bs + (kb & 1) * FB_TILEH;
        #pragma unroll
        for (int kk = 0; kk < 2; kk++) {
            wmma::fragment<wmma::matrix_a, 16, 16, 16, __half, wmma::row_major> af[2];
            wmma::fragment<wmma::matrix_b, 16, 16, 16, __half, wmma::col_major> bf[4];
            #pragma unroll
            for (int i = 0; i < 2; i++)
                wmma::load_matrix_sync(af[i], a_base + (mw + i * 16) * FB_LD + kk * 16, FB_LD);
            #pragma unroll
            for (int j = 0; j < 4; j++)
                wmma::load_matrix_sync(bf[j], b_base + (nw + j * 16) * FB_LD + kk * 16, FB_LD);
            #pragma unroll
            for (int i = 0; i < 2; i++)
                #pragma unroll
                for (int j = 0; j < 4; j++)
                    wmma::mma_sync(acc[i][j], af[i], bf[j], acc[i][j]);
        }
        __syncthreads();
    }

    const float* bias = (e == 0) ? bias0 : bias1;
    #pragma unroll
    for (int i = 0; i < 2; i++) {
        #pragma unroll
        for (int j = 0; j < 4; j++) {
            wmma::store_matrix_sync(staging, acc[i][j], 20, wmma::mem_row_major);
            __syncwarp();
            const int r  = lane >> 1;
            const int ch = (lane & 1) * 8;
            const int gm = m0 + mw + i * 16 + r;
            const int gn = n0 + nw + j * 16 + ch;
            const bool msk = (type_ids[gm] == e);
            float* op = out + ((size_t)e * ROWS_T + gm) * OUTD + gn;
            float4 v0, v1;
            if (msk) {
                const float* sp = staging + r * 20 + ch;
                v0.x = sp[0] + bias[gn + 0]; v0.y = sp[1] + bias[gn + 1];
                v0.z = sp[2] + bias[gn + 2]; v0.w = sp[3] + bias[gn + 3];
                v1.x = sp[4] + bias[gn + 4]; v1.y = sp[5] + bias[gn + 5];
                v1.z = sp[6] + bias[gn + 6]; v1.w = sp[7] + bias[gn + 7];
            } else {
                v0.x = v0.y = v0.z = v0.w = 0.f;
                v1.x = v1.y = v1.z = v1.w = 0.f;
            }
            *reinterpret_cast<float4*>(op)     = v0;
            *reinterpret_cast<float4*>(op + 4) = v1;
            __syncwarp();
        }
    }
#endif  // !TC_PATH
}

// ---------------- launch ----------------
extern "C" void kernel_launch(void* const* d_in, const int* in_sizes, int n_in,
                              void* d_out, int out_size) {
    (void)in_sizes; (void)n_in; (void)out_size;
    const float* x   = (const float*)d_in[0];
    const int*   tti = (const int*)d_in[1];
    const float* W0  = (const float*)d_in[2];
    const float* b0  = (const float*)d_in[3];
    const float* W1  = (const float*)d_in[4];
    const float* b1  = (const float*)d_in[5];
    float* out = (float*)d_out;

    // fp32 -> fp16 operand prep (needed by both paths)
    conv_x_kernel<<<(ROWS_T * (DK / 4)) / 256, 256>>>(x);
    dim3 wgrid(OUTD / 32, DK / 32);
    conv_w_kernel<<<wgrid, dim3(32, 8)>>>(W0, 0);
    conv_w_kernel<<<wgrid, dim3(32, 8)>>>(W1, 1);

    cudaFuncSetAttribute(motmod_gemm_kernel,
                         cudaFuncAttributeMaxDynamicSharedMemorySize, SMEM_TOTAL);
    cudaFuncSetAttribute(motmod_wmma_kernel,
                         cudaFuncAttributeMaxDynamicSharedMemorySize, FB_SMEM);

    // tcgen05 path (real body only in the sm_103a image; no-op elsewhere)
    dim3 grid_tc(OUTD / NT, ROWS_T / MT, NEXP);                // 16 x 64 x 2 = 2048 CTAs
    motmod_gemm_kernel<<<grid_tc, 256, SMEM_TOTAL>>>(tti, b0, b1, out);

    // wmma fallback (real body only in non-accel images; no-op on sm_103a)
    dim3 grid_fb(OUTD / 128, ROWS_T / 128, NEXP);
    motmod_wmma_kernel<<<grid_fb, 256, FB_SMEM>>>(tti, b0, b1, out);
}

// round 17
// speedup vs baseline: 1.4534x; 1.3915x over previous
#include <cuda_runtime.h>
#include <cuda_fp16.h>
#include <mma.h>
#include <cstdint>
#include <cstddef>

// ---------------- arch-conditional path selection ----------------
#if defined(__CUDA_ARCH__) && \
    (defined(__CUDA_ARCH_FEAT_SM103_ALL) || defined(__CUDA_ARCH_FEAT_SM100_ALL) || \
     defined(__CUDA_ARCH_SPECIFIC__) || defined(__CUDA_ARCH_FAMILY_SPECIFIC__))
#define TC_PATH 1
#else
#define TC_PATH 0
#endif

// ---------------- problem dims ----------------
#define ROWS_T 16384   // B*S
#define DK     1024    // d_model (K)
#define OUTD   4096    // out_dim (N total)
#define NEXP   2       // modalities

// ---------------- tcgen05 tiling (R16: gathered tokens) ----------------
#define MT 256         // M tile (compacted token rows) = 2 x M=128 MMA sub-tiles
#define NT 256         // N tile = 2 x N=128 MMA atoms
#define KC 64          // K chunk (64 halves = 128B SW128 rows)
#define NKC (DK / KC)  // 16
#define ST 3           // pipeline stages

#define STAGE_A_BYTES (MT * 128)            // 32 KB
#define STAGE_B_BYTES (NT * 128)            // 32 KB
#define STAGE_BYTES   (STAGE_A_BYTES + STAGE_B_BYTES)      // 64 KB
#define SMEM_TOTAL    (3200 + ST * STAGE_BYTES)            // 199808 B -> 1 CTA/SM

// idesc kind::f16: dtype=F32 (bit4), atype=btype=F16 (0), N=128 -> 16<<17, M=128 -> 8<<24
#define IDESC_F16 ((1u << 4) | (16u << 17) | (8u << 24))

// ---------------- fallback (wmma) tiling ----------------
#define FB_LD    40
#define FB_TILEH (128 * FB_LD)
#define FB_SMEM  (4 * FB_TILEH * 2 + 8 * 16 * 20 * 4)

// ---------------- scratch ----------------
__device__ __half g_Xh[(size_t)ROWS_T * DK];          // X cast to fp16, row-major [ROWS, DK]
__device__ __half g_Wt[(size_t)NEXP * OUTD * DK];     // W transposed to [OUT, DK] K-major, fp16
__device__ int    g_idx[NEXP][ROWS_T];                // compacted routed row indices per expert
__device__ int    g_cnt[NEXP];                        // routed token counts

// ---------------- generic helpers ----------------
__device__ __forceinline__ uint32_t smem_u32(const void* p) {
    uint32_t a;
    asm("{ .reg .u64 t; cvta.to.shared.u64 t, %1; cvt.u32.u64 %0, t; }" : "=r"(a) : "l"(p));
    return a;
}

#define SWZ(o) ((o) ^ (((o) >> 3) & 0x70))

__device__ __forceinline__ void cp_async16(uint32_t dst_smem, const void* src) {
    asm volatile("cp.async.cg.shared.global [%0], [%1], 16;" :: "r"(dst_smem), "l"(src));
}
#define CP_COMMIT() asm volatile("cp.async.commit_group;" ::: "memory")
#define CP_WAIT0()  asm volatile("cp.async.wait_group 0;"  ::: "memory")

__device__ __forceinline__ void cpasync_mbar_arrive_noinc(uint32_t mbar) {
    asm volatile("cp.async.mbarrier.arrive.noinc.shared::cta.b64 [%0];" :: "r"(mbar) : "memory");
}

__device__ __forceinline__ void mbar_init(uint32_t mbar, uint32_t count) {
    asm volatile("mbarrier.init.shared.b64 [%0], %1;" :: "r"(mbar), "r"(count) : "memory");
}

__device__ __forceinline__ void mbar_wait(uint32_t mbar, uint32_t parity) {
    asm volatile(
        "{\n\t.reg .pred P;\n"
        "WL_%=:\n\t"
        "mbarrier.try_wait.parity.acquire.cta.shared::cta.b64 P, [%0], %1, 0x989680;\n\t"
        "@P bra.uni WD_%=;\n\t"
        "bra.uni WL_%=;\n"
        "WD_%=:\n\t}"
        :: "r"(mbar), "r"(parity) : "memory");
}

// ---------------- prep kernels ----------------
__global__ void conv_x_kernel(const float* __restrict__ x) {
    if (blockIdx.x == 0 && threadIdx.x == 0) { g_cnt[0] = 0; g_cnt[1] = 0; }
    size_t i = (size_t)blockIdx.x * blockDim.x + threadIdx.x;
    float4 v = reinterpret_cast<const float4*>(x)[i];
    __half2* o = reinterpret_cast<__half2*>(g_Xh);
    o[i * 2 + 0] = __floats2half2_rn(v.x, v.y);
    o[i * 2 + 1] = __floats2half2_rn(v.z, v.w);
}

// W [DK, OUTD] fp32 row-major  ->  g_Wt[e] [OUT, DK] fp16 K-major (transpose + cast)
__global__ void conv_w_kernel(const float* __restrict__ W, int e) {
    __shared__ float t[32][33];
    int o0 = blockIdx.x * 32, d0 = blockIdx.y * 32;
    int tx = threadIdx.x, ty = threadIdx.y;   // (32, 8)
    #pragma unroll
    for (int j = 0; j < 32; j += 8)
        t[ty + j][tx] = W[(size_t)(d0 + ty + j) * OUTD + o0 + tx];
    __syncthreads();
    __half* Wt = g_Wt + (size_t)e * OUTD * DK;
    #pragma unroll
    for (int j = 0; j < 32; j += 8)
        Wt[(size_t)(o0 + ty + j) * DK + d0 + tx] = __float2half(t[tx][ty + j]);
}

// Compact routed token indices per expert (warp-aggregated atomics).
// Ordering is atomic-arrival-dependent, but every ordering yields bitwise
// identical output (each row's GEMM result is independent of tile placement).
__global__ void build_index_kernel(const int* __restrict__ type_ids) {
    int i = blockIdx.x * blockDim.x + threadIdx.x;
    int e = type_ids[i];
    int lane = threadIdx.x & 31;
    unsigned m1 = __ballot_sync(0xffffffffu, e == 1);
    unsigned below = (lane == 0) ? 0u : (0xffffffffu >> (32 - lane));
    int base0 = 0, base1 = 0;
    if (lane == 0) {
        base0 = atomicAdd(&g_cnt[0], 32 - __popc(m1));
        base1 = atomicAdd(&g_cnt[1], __popc(m1));
    }
    base0 = __shfl_sync(0xffffffffu, base0, 0);
    base1 = __shfl_sync(0xffffffffu, base1, 0);
    int rank = (e == 1) ? __popc(m1 & below) : __popc(~m1 & below);
    g_idx[e][(e == 1 ? base1 : base0) + rank] = i;
}

// Zero the output rows NOT routed to expert e (disjoint from GEMM writes).
__global__ void zero_fill_kernel(const int* __restrict__ type_ids,
                                 float* __restrict__ out) {
    int row = blockIdx.x, e = blockIdx.y;
    if (type_ids[row] == e) return;
    float4* p = reinterpret_cast<float4*>(out + ((size_t)e * ROWS_T + row) * OUTD);
    float4 z = {0.f, 0.f, 0.f, 0.f};
    #pragma unroll
    for (int j = threadIdx.x; j < OUTD / 4; j += 256) p[j] = z;
}

// ===================================================================
//                    tcgen05 path (sm_103a only)
// ===================================================================
#if TC_PATH
__device__ __forceinline__ uint64_t make_desc_sw128(uint32_t addr) {
    // layout=SW128(2), version=1 (Blackwell), SBO=64, LBO=1
    const uint64_t base = (uint64_t(2) << 61) | (uint64_t(1) << 46) |
                          (uint64_t(64) << 32) | (uint64_t(1) << 16);
    return base | ((uint64_t)(addr >> 4) & 0x3FFF);
}

__device__ __forceinline__ void tcgen05_mma_f16_ss(uint32_t d_tmem, uint64_t a_desc,
                                                   uint64_t b_desc, uint32_t idesc,
                                                   uint32_t enable_d) {
    asm volatile(
        "{\n\t.reg .pred p;\n\t"
        "setp.ne.u32 p, %5, 0;\n\t"
        "tcgen05.mma.cta_group::1.kind::f16 [%0], %1, %2, %3, {%4, %4, %4, %4}, p;\n\t}"
        :: "r"(d_tmem), "l"(a_desc), "l"(b_desc), "r"(idesc), "r"(0u), "r"(enable_d)
        : "memory");
}

#define TC_COMMIT(mbar) \
    asm volatile("tcgen05.commit.cta_group::1.mbarrier::arrive::one.shared::cluster.b64 [%0];" \
                 :: "r"(mbar) : "memory")
#define TC_ALLOC(dst_smem, ncols) \
    asm volatile("tcgen05.alloc.cta_group::1.sync.aligned.shared::cta.b32 [%0], %1;" \
                 :: "r"(dst_smem), "r"(ncols) : "memory")
#define TC_DEALLOC(tmem, ncols) \
    asm volatile("tcgen05.dealloc.cta_group::1.sync.aligned.b32 %0, %1;" :: "r"(tmem), "r"(ncols))
#define TC_RELINQ() \
    asm volatile("tcgen05.relinquish_alloc_permit.cta_group::1.sync.aligned;")
#define TC_FENCE_AFTER()  asm volatile("tcgen05.fence::after_thread_sync;" ::: "memory")
#define TC_FENCE_BEFORE() asm volatile("tcgen05.fence::before_thread_sync;" ::: "memory")
#define TC_WAIT_LD()      asm volatile("tcgen05.wait::ld.sync.aligned;" ::: "memory")
#define FENCE_PROXY_ASYNC() asm volatile("fence.proxy.async.shared::cta;" ::: "memory")

#define TC_LD_32X32B_X32(r, tmem_addr) \
    asm volatile( \
        "tcgen05.ld.sync.aligned.32x32b.x32.b32 " \
        "{%0, %1, %2, %3, %4, %5, %6, %7, " \
        " %8, %9, %10, %11, %12, %13, %14, %15, " \
        " %16, %17, %18, %19, %20, %21, %22, %23, " \
        " %24, %25, %26, %27, %28, %29, %30, %31}, [%32];" \
        : "=r"((r)[0]),  "=r"((r)[1]),  "=r"((r)[2]),  "=r"((r)[3]), \
          "=r"((r)[4]),  "=r"((r)[5]),  "=r"((r)[6]),  "=r"((r)[7]), \
          "=r"((r)[8]),  "=r"((r)[9]),  "=r"((r)[10]), "=r"((r)[11]), \
          "=r"((r)[12]), "=r"((r)[13]), "=r"((r)[14]), "=r"((r)[15]), \
          "=r"((r)[16]), "=r"((r)[17]), "=r"((r)[18]), "=r"((r)[19]), \
          "=r"((r)[20]), "=r"((r)[21]), "=r"((r)[22]), "=r"((r)[23]), \
          "=r"((r)[24]), "=r"((r)[25]), "=r"((r)[26]), "=r"((r)[27]), \
          "=r"((r)[28]), "=r"((r)[29]), "=r"((r)[30]), "=r"((r)[31]) \
        : "r"(tmem_addr))
#endif  // TC_PATH

// smem control block (offsets from smem_base):
//   +0   : TMEM base pointer
//   +16  : full[0..2]   (producers -> MMA, count 128, cp.async tracked)
//   +48  : empty[0..2]  (MMA commit -> producers, count 1)
//   +80  : done         (final MMA commit, count 1)
//   +128 : idx list, 256 ints (compacted global row per tile-local row)
#define MB_FULL(s)  (smem_base + 16 + (s) * 8)
#define MB_EMPTY(s) (smem_base + 48 + (s) * 8)
#define MB_DONE     (smem_base + 80)

__global__ __launch_bounds__(256, 1)
void motmod_gemm_kernel(const int* __restrict__ type_ids,
                        const float* __restrict__ bias0,
                        const float* __restrict__ bias1,
                        float* __restrict__ out) {
#if TC_PATH
    extern __shared__ __align__(16) char smem[];
    const uint32_t smem_base = smem_u32(smem);
    const uint32_t data_base = (smem_base + 1152u + 1023u) & ~1023u;   // 1024B-aligned tiles
    int* idx_sm = reinterpret_cast<int*>(smem + 128);
    const int tid = threadIdx.x;
    const int wid = tid >> 5, lid = tid & 31;

    const int n0 = blockIdx.x * NT;
    const int m0 = blockIdx.y * MT;
    const int e  = blockIdx.z;

    const int cnt = g_cnt[e];
    if (m0 >= cnt) return;                          // tile fully beyond routed tokens

    if (wid == 0) {
        TC_ALLOC(smem_base, 512);                   // 2 M-subtiles x 256 TMEM cols
        TC_RELINQ();
    }
    if (tid == 0) {
        #pragma unroll
        for (int s = 0; s < ST; s++) {
            mbar_init(MB_FULL(s), 128);             // 128 producer threads
            mbar_init(MB_EMPTY(s), 1);              // one tcgen05.commit
        }
        mbar_init(MB_DONE, 1);
    }
    // stage compacted row indices (clamped; padding rows never stored)
    {
        int g = m0 + tid;
        idx_sm[tid] = g_idx[e][g < cnt ? g : cnt - 1];
    }
    __syncthreads();

    uint32_t tmem_base;
    asm volatile("ld.shared.b32 %0, [%1];" : "=r"(tmem_base) : "r"(smem_base));

    const __half* Bsrc = g_Wt + ((size_t)e * OUTD + n0) * DK;

    if (tid >= 128) {
        // ---------------- producer: warps 4-7, free-running ----------------
        const int p = tid - 128;                    // 0..127
        for (int c = 0; c < NKC; c++) {
            const int s = c % ST;
            if (c >= ST) mbar_wait(MB_EMPTY(s), ((c / ST) - 1) & 1);
            const uint32_t aBase = data_base + (uint32_t)s * STAGE_BYTES;
            const uint32_t bBase = aBase + STAGE_A_BYTES;
            const int k0 = c * KC;
            // A: 256 gathered rows x 8 x 16B = 2048 vectors, 16 per thread
            #pragma unroll
            for (int t = 0; t < 16; t++) {
                int idx = p + t * 128;
                int row = idx >> 3, ch = idx & 7;
                cp_async16(aBase + SWZ((uint32_t)(row * 128 + ch * 16)),
                           g_Xh + (size_t)idx_sm[row] * DK + k0 + ch * 8);
            }
            // B: 256 rows x 8 x 16B = 2048 vectors, 16 per thread
            #pragma unroll
            for (int t = 0; t < 16; t++) {
                int idx = p + t * 128;
                int row = idx >> 3, ch = idx & 7;
                cp_async16(bBase + SWZ((uint32_t)(row * 128 + ch * 16)),
                           Bsrc + (size_t)row * DK + k0 + ch * 8);
            }
            cpasync_mbar_arrive_noinc(MB_FULL(s));  // arrive when the above land
        }
    } else if (wid == 0 && lid == 0) {
        // ---------------- MMA issuer: single thread, free-running ----------------
        for (int c = 0; c < NKC; c++) {
            const int s = c % ST;
            mbar_wait(MB_FULL(s), (c / ST) & 1);
            FENCE_PROXY_ASYNC();
            const uint32_t aBase = data_base + (uint32_t)s * STAGE_BYTES;
            const uint32_t bBase = aBase + STAGE_A_BYTES;
            const uint64_t ad = make_desc_sw128(aBase);
            const uint64_t bd = make_desc_sw128(bBase);
            #pragma unroll
            for (int ks = 0; ks < 4; ks++) {                  // K=16 per MMA
                const uint32_t acc = (c > 0 || ks > 0) ? 1u : 0u;
                #pragma unroll
                for (int mt = 0; mt < 2; mt++) {
                    #pragma unroll
                    for (int h = 0; h < 2; h++) {
                        tcgen05_mma_f16_ss(tmem_base + mt * 256 + h * 128,
                                           ad + (uint64_t)mt * 1024 + ks * 2,
                                           bd + (uint64_t)h  * 1024 + ks * 2,
                                           IDESC_F16, acc);
                    }
                }
            }
            TC_COMMIT(MB_EMPTY(s));
        }
        TC_COMMIT(MB_DONE);
    }

    // ---------------- epilogue: all 8 warps, scatter to original rows ----------------
    mbar_wait(MB_DONE, 0);
    TC_FENCE_AFTER();

    const int mt   = wid >> 2;
    const int wsub = wid & 3;
    const int lr   = mt * 128 + wsub * 32 + lid;               // tile-local row
    const int valid = (m0 + lr) < cnt;
    const int r = idx_sm[lr];                                  // original global row
    const float* bias = ((e == 0) ? bias0 : bias1) + n0;
    float* orow = out + ((size_t)e * ROWS_T + r) * OUTD + n0;
    const uint32_t treg = tmem_base + mt * 256;

    #pragma unroll
    for (int cb = 0; cb < 8; cb++) {                           // 8 x 32 cols
        uint32_t dr[32];
        TC_LD_32X32B_X32(dr, treg + cb * 32);
        TC_WAIT_LD();
        if (valid) {
            const int c0 = cb * 32;
            #pragma unroll
            for (int j = 0; j < 32; j += 4) {
                float4 v;
                v.x = __uint_as_float(dr[j + 0]) + __ldg(&bias[c0 + j + 0]);
                v.y = __uint_as_float(dr[j + 1]) + __ldg(&bias[c0 + j + 1]);
                v.z = __uint_as_float(dr[j + 2]) + __ldg(&bias[c0 + j + 2]);
                v.w = __uint_as_float(dr[j + 3]) + __ldg(&bias[c0 + j + 3]);
                *reinterpret_cast<float4*>(orow + c0 + j) = v;
            }
        }
    }
    TC_FENCE_BEFORE();

    __syncthreads();
    if (wid == 0) TC_DEALLOC(tmem_base, 512);
#endif  // TC_PATH
}

// ===================================================================
//       wmma fallback (dense + mask; compiled when tcgen05 unavailable)
// ===================================================================
__global__ __launch_bounds__(256, 2)
void motmod_wmma_kernel(const int* __restrict__ type_ids,
                        const float* __restrict__ bias0,
                        const float* __restrict__ bias1,
                        float* __restrict__ out) {
#if !TC_PATH && defined(__CUDA_ARCH__)
    using namespace nvcuda;
    extern __shared__ __align__(16) char fsmem_raw[];
    __half* fsmem = reinterpret_cast<__half*>(fsmem_raw);

    const int tid = threadIdx.x, wid = tid >> 5, lane = tid & 31;
    const int n0 = blockIdx.x * 128;
    const int m0 = blockIdx.y * 128;
    const int e  = blockIdx.z;

    __half* As = fsmem;
    __half* Bs = fsmem + 2 * FB_TILEH;
    float* staging = reinterpret_cast<float*>(fsmem + 4 * FB_TILEH) + wid * 16 * 20;

    const __half* Ag = g_Xh + (size_t)m0 * DK;
    const __half* Bg = g_Wt + ((size_t)e * OUTD + n0) * DK;

    const uint32_t As_u = smem_u32(As);
    const uint32_t Bs_u = smem_u32(Bs);

    auto load_tiles = [&](int s, int k0) {
        #pragma unroll
        for (int t = 0; t < 2; t++) {
            int idx = tid + t * 256;
            int row = idx >> 2, c = idx & 3;
            uint32_t off = (uint32_t)((s * FB_TILEH + row * FB_LD + c * 8) * 2);
            cp_async16(As_u + off, Ag + (size_t)row * DK + k0 + c * 8);
            cp_async16(Bs_u + off, Bg + (size_t)row * DK + k0 + c * 8);
        }
        CP_COMMIT();
    };

    wmma::fragment<wmma::accumulator, 16, 16, 16, float> acc[2][4];
    #pragma unroll
    for (int i = 0; i < 2; i++)
        #pragma unroll
        for (int j = 0; j < 4; j++) wmma::fill_fragment(acc[i][j], 0.0f);

    const int wy = wid & 3, wx = wid >> 2;
    const int mw = wy * 32, nw = wx * 64;

    load_tiles(0, 0);
    for (int kb = 0; kb < DK / 32; kb++) {
        CP_WAIT0();
        __syncthreads();
        if (kb + 1 < DK / 32) load_tiles((kb + 1) & 1, (kb + 1) * 32);

        const __half* a_base = As + (kb & 1) * FB_TILEH;
        const __half* b_base = Bs + (kb & 1) * FB_TILEH;
        #pragma unroll
        for (int kk = 0; kk < 2; kk++) {
            wmma::fragment<wmma::matrix_a, 16, 16, 16, __half, wmma::row_major> af[2];
            wmma::fragment<wmma::matrix_b, 16, 16, 16, __half, wmma::col_major> bf[4];
            #pragma unroll
            for (int i = 0; i < 2; i++)
                wmma::load_matrix_sync(af[i], a_base + (mw + i * 16) * FB_LD + kk * 16, FB_LD);
            #pragma unroll
            for (int j = 0; j < 4; j++)
                wmma::load_matrix_sync(bf[j], b_base + (nw + j * 16) * FB_LD + kk * 16, FB_LD);
            #pragma unroll
            for (int i = 0; i < 2; i++)
                #pragma unroll
                for (int j = 0; j < 4; j++)
                    wmma::mma_sync(acc[i][j], af[i], bf[j], acc[i][j]);
        }
        __syncthreads();
    }

    const float* bias = (e == 0) ? bias0 : bias1;
    #pragma unroll
    for (int i = 0; i < 2; i++) {
        #pragma unroll
        for (int j = 0; j < 4; j++) {
            wmma::store_matrix_sync(staging, acc[i][j], 20, wmma::mem_row_major);
            __syncwarp();
            const int r  = lane >> 1;
            const int ch = (lane & 1) * 8;
            const int gm = m0 + mw + i * 16 + r;
            const int gn = n0 + nw + j * 16 + ch;
            const bool msk = (type_ids[gm] == e);
            float* op = out + ((size_t)e * ROWS_T + gm) * OUTD + gn;
            float4 v0, v1;
            if (msk) {
                const float* sp = staging + r * 20 + ch;
                v0.x = sp[0] + bias[gn + 0]; v0.y = sp[1] + bias[gn + 1];
                v0.z = sp[2] + bias[gn + 2]; v0.w = sp[3] + bias[gn + 3];
                v1.x = sp[4] + bias[gn + 4]; v1.y = sp[5] + bias[gn + 5];
                v1.z = sp[6] + bias[gn + 6]; v1.w = sp[7] + bias[gn + 7];
            } else {
                v0.x = v0.y = v0.z = v0.w = 0.f;
                v1.x = v1.y = v1.z = v1.w = 0.f;
            }
            *reinterpret_cast<float4*>(op)     = v0;
            *reinterpret_cast<float4*>(op + 4) = v1;
            __syncwarp();
        }
    }
#endif  // !TC_PATH
}

// ---------------- launch ----------------
extern "C" void kernel_launch(void* const* d_in, const int* in_sizes, int n_in,
                              void* d_out, int out_size) {
    (void)in_sizes; (void)n_in; (void)out_size;
    const float* x   = (const float*)d_in[0];
    const int*   tti = (const int*)d_in[1];
    const float* W0  = (const float*)d_in[2];
    const float* b0  = (const float*)d_in[3];
    const float* W1  = (const float*)d_in[4];
    const float* b1  = (const float*)d_in[5];
    float* out = (float*)d_out;

    // prep: cast X (also resets g_cnt), cast+transpose W, build gather index,
    // zero non-routed output rows
    conv_x_kernel<<<(ROWS_T * (DK / 4)) / 256, 256>>>(x);
    dim3 wgrid(OUTD / 32, DK / 32);
    conv_w_kernel<<<wgrid, dim3(32, 8)>>>(W0, 0);
    conv_w_kernel<<<wgrid, dim3(32, 8)>>>(W1, 1);
    build_index_kernel<<<ROWS_T / 256, 256>>>(tti);
    zero_fill_kernel<<<dim3(ROWS_T, NEXP), 256>>>(tti, out);

    cudaFuncSetAttribute(motmod_gemm_kernel,
                         cudaFuncAttributeMaxDynamicSharedMemorySize, SMEM_TOTAL);
    cudaFuncSetAttribute(motmod_wmma_kernel,
                         cudaFuncAttributeMaxDynamicSharedMemorySize, FB_SMEM);

    // tcgen05 path: grid.y sized for worst-case routing; extra CTAs exit early
    dim3 grid_tc(OUTD / NT, ROWS_T / MT, NEXP);                // 16 x 64 x 2
    motmod_gemm_kernel<<<grid_tc, 256, SMEM_TOTAL>>>(tti, b0, b1, out);

    // wmma fallback (real body only in non-accel images; no-op on sm_103a).
    // Dense+mask: its masked-row zero writes coincide with zero_fill values.
    dim3 grid_fb(OUTD / 128, ROWS_T / 128, NEXP);
    motmod_wmma_kernel<<<grid_fb, 256, FB_SMEM>>>(tti, b0, b1, out);
}